// round 14
// baseline (speedup 1.0000x reference)
#include <cuda_runtime.h>

#define NPTS 131072
#define DD 32
#define KK 64
#define B2E 14.426950408889634f  /* BETA * log2(e), BETA=10 */
#define NBLK2 740                /* k_assign grid: 5 blocks/SM */
#define NWARPS (NBLK2 * 8)       /* 5920 counting warps */
#define NREP 32                  /* scatter cursor replicas */
#define TILE2 128                /* k_cov tile rows */

// ---------------- device scratch (zero-initialized at load; every kernel
// leaves its accumulators re-zeroed => graph replays start clean) ----------
__device__ int   g_ord[NPTS];              // cluster-sorted permutation
__device__ unsigned char g_pred[NPTS];
__device__ int   g_counts[KK];
__device__ int   g_counts2[KK * NREP];
__device__ int   g_cursor2[KK * NREP];
__device__ int   g_offsets[KK + 1];
__device__ float g_fil[KK];
__device__ float g_sums[KK * DD];
__device__ float g_m2[KK * DD * DD];
__device__ float g_acc[2];

// order-preserving float<->u32 key (min of key == min of float, bijective)
__device__ __forceinline__ unsigned ordkey(float f) {
    unsigned u = __float_as_uint(f);
    return u ^ (unsigned)(((int)u >> 31) | 0x80000000);
}
__device__ __forceinline__ float unord(unsigned k) {
    unsigned u = (k & 0x80000000u) ? (k ^ 0x80000000u) : ~k;
    return __uint_as_float(u);
}

// ---------------- K1: logits, softmax-filling, argmin, histogram ----------------
__global__ __launch_bounds__(256, 5)
void k_assign(const float* __restrict__ x, const float* __restrict__ centers) {
    __shared__ float sc[KK * DD];     // swizzled centers
    __shared__ float scn[KK];
    __shared__ float sfil[KK];
    __shared__ int   shist[KK];
    __shared__ float sxw[8][4][DD];

    int t = threadIdx.x, w = t >> 5, l = t & 31;

#pragma unroll
    for (int v = 0; v < 2; v++) {
        int idx = v * 256 + t;
        int r = idx >> 3, q = idx & 7;
        float4 val = ((const float4*)centers)[idx];
        int qs = q ^ (r & 7);
        *(float4*)&sc[r * DD + qs * 4] = val;
    }
    __syncthreads();
    if (t < KK) {
        float a = 0.f;
#pragma unroll
        for (int q = 0; q < 8; q++) {
            int qs = q ^ (t & 7);
            float4 v = *(const float4*)&sc[t * DD + qs * 4];
            a = fmaf(v.x, v.x, fmaf(v.y, v.y, fmaf(v.z, v.z, fmaf(v.w, v.w, a))));
        }
        scn[t] = a;
        sfil[t] = 0.f; shist[t] = 0;
    }
    __syncthreads();

    float cn0 = scn[l], cn1 = scn[l + 32];
    const float* c0base = sc + l * DD;
    const float* c1base = sc + (l + 32) * DD;
    int sw = (l & 7);

    float fil0 = 0.f, fil1 = 0.f;
    int W = blockIdx.x * 8 + w;

    for (int n0 = W * 4; n0 < NPTS; n0 += NWARPS * 4) {
        float xp[4];
#pragma unroll
        for (int p = 0; p < 4; p++) xp[p] = x[(size_t)(n0 + p) * DD + l];
        __syncwarp();
#pragma unroll
        for (int p = 0; p < 4; p++) sxw[w][p][l] = xp[p];
        __syncwarp();

        float d0[4] = {0.f, 0.f, 0.f, 0.f};
        float d1[4] = {0.f, 0.f, 0.f, 0.f};
#pragma unroll
        for (int q = 0; q < 8; q++) {
            int qs = (q ^ sw) * 4;
            float4 cv0 = *(const float4*)&c0base[qs];
            float4 cv1 = *(const float4*)&c1base[qs];
#pragma unroll
            for (int p = 0; p < 4; p++) {
                float4 xv = *(const float4*)&sxw[w][p][q * 4];
                d0[p] = fmaf(cv0.x, xv.x, d0[p]);
                d0[p] = fmaf(cv0.y, xv.y, d0[p]);
                d0[p] = fmaf(cv0.z, xv.z, d0[p]);
                d0[p] = fmaf(cv0.w, xv.w, d0[p]);
                d1[p] = fmaf(cv1.x, xv.x, d1[p]);
                d1[p] = fmaf(cv1.y, xv.y, d1[p]);
                d1[p] = fmaf(cv1.z, xv.z, d1[p]);
                d1[p] = fmaf(cv1.w, xv.w, d1[p]);
            }
        }

        float s0a[4], s1a[4];
#pragma unroll
        for (int p = 0; p < 4; p++) {
            s0a[p] = fmaf(-2.f, d0[p], cn0);
            s1a[p] = fmaf(-2.f, d1[p], cn1);
        }

        unsigned k0v[4], k1v[4], mk[4];
#pragma unroll
        for (int p = 0; p < 4; p++) { k0v[p] = ordkey(s0a[p]); k1v[p] = ordkey(s1a[p]); }
#pragma unroll
        for (int p = 0; p < 4; p++)
            mk[p] = __reduce_min_sync(0xffffffffu, min(k0v[p], k1v[p]));
        int id[4];
#pragma unroll
        for (int p = 0; p < 4; p++) {
            unsigned cand = (k0v[p] == mk[p]) ? (unsigned)l
                          : ((k1v[p] == mk[p]) ? (unsigned)(l + 32) : 1024u);
            id[p] = (int)__reduce_min_sync(0xffffffffu, cand);
        }

        float e0[4], e1[4], es[4];
#pragma unroll
        for (int p = 0; p < 4; p++) {
            float mn = unord(mk[p]);
            asm("ex2.approx.f32 %0, %1;" : "=f"(e0[p]) : "f"((mn - s0a[p]) * B2E));
            asm("ex2.approx.f32 %0, %1;" : "=f"(e1[p]) : "f"((mn - s1a[p]) * B2E));
            es[p] = e0[p] + e1[p];
        }
#pragma unroll
        for (int off = 16; off; off >>= 1) {
#pragma unroll
            for (int p = 0; p < 4; p++)
                es[p] += __shfl_xor_sync(0xffffffffu, es[p], off);
        }

        unsigned pred4 = 0;
#pragma unroll
        for (int p = 0; p < 4; p++) {
            float inv;
            asm("rcp.approx.f32 %0, %1;" : "=f"(inv) : "f"(es[p]));
            fil0 = fmaf(e0[p], inv, fil0);
            fil1 = fmaf(e1[p], inv, fil1);
            pred4 |= (unsigned)id[p] << (8 * p);
            if (l == p) atomicAdd(&shist[id[p]], 1);
        }
        if (l == 0) *(unsigned*)(g_pred + n0) = pred4;
    }

    atomicAdd(&sfil[l], fil0);
    atomicAdd(&sfil[l + 32], fil1);
    __syncthreads();
    if (t < KK) {
        atomicAdd(&g_fil[t], sfil[t]);
        atomicAdd(&g_counts2[t * NREP + (blockIdx.x & (NREP - 1))], shist[t]);
    }
}

// ---------------- K2: prefix over 64 clusters x 32 replicas (+re-zero) ----------------
__global__ void k_prefix() {
    __shared__ int csum[KK];
    int t = threadIdx.x;   // 64 threads
    int c[NREP];
    int total = 0;
#pragma unroll
    for (int r = 0; r < NREP; r++) {
        c[r] = g_counts2[t * NREP + r];
        g_counts2[t * NREP + r] = 0;
        total += c[r];
    }
    csum[t] = total;
    __syncthreads();
    if (t == 0) {
        int a = 0;
        for (int k = 0; k < KK; k++) { g_offsets[k] = a; a += csum[k]; }
        g_offsets[KK] = a;
    }
    __syncthreads();
    int a = g_offsets[t];
#pragma unroll
    for (int r = 0; r < NREP; r++) { g_cursor2[t * NREP + r] = a; a += c[r]; }
    g_counts[t] = total;
}

// ---------------- K3: permutation only (no data movement) ----------------
__global__ __launch_bounds__(256)
void k_order() {
    int i0 = (blockIdx.x * 256 + threadIdx.x) * 4;
    if (i0 >= NPTS) return;
    unsigned pr = *(const unsigned*)(g_pred + i0);
    int rep = (((i0 >> 2) % NWARPS) >> 3) & (NREP - 1);
#pragma unroll
    for (int p = 0; p < 4; p++) {
        int k = (pr >> (8 * p)) & 255;
        int pos = atomicAdd(&g_cursor2[k * NREP + rep], 1);
        g_ord[pos] = i0 + p;
    }
}

// ---------------- K4: 128-row tiles; warp-owned 4x8 register blocks ----------------
// Each warp covers the FULL 32x32 output (lane: 4 rows x 8 cols, 32 accums)
// over its quarter of the points (1.5 B LDS per FMA). Single-segment tiles
// (~94%) merge the 4 warps via smem then issue 1024 atomics; boundary tiles
// use direct per-warp atomics.
__global__ __launch_bounds__(128)
void k_cov(const float* __restrict__ x) {
    __shared__ float sx[TILE2 * DD];          // 16 KB tile
    __shared__ float sm[4 * 32 * 32];         // 16 KB merge buffer
    __shared__ int sord[TILE2];
    int t = threadIdx.x, w = t >> 5, l = t & 31;
    int p0 = blockIdx.x * TILE2;

    sord[t] = g_ord[p0 + t];
    __syncthreads();

    {   // gather tile: 8 consecutive threads read same row, consecutive chunks
        float4* sv = (float4*)sx;
        const float4* xv = (const float4*)x;
#pragma unroll
        for (int v = 0; v < 8; v++) {
            int li = v * 128 + t;              // 0..1023
            int row = li >> 3, chunk = li & 7;
            sv[li] = xv[(size_t)sord[row] * 8 + chunk];
        }
    }
    __syncthreads();

    // cluster containing row p0
    int lo_c = 0, hi_c = KK;
    while (lo_c + 1 < hi_c) {
        int mid = (lo_c + hi_c) >> 1;
        if (g_offsets[mid] <= p0) lo_c = mid; else hi_c = mid;
    }
    int c = lo_c;

    int r4 = (l >> 2) * 4;     // 4-row base
    int c8 = (l & 3) * 8;      // 8-col base
    int wlo = w * 32, whi = wlo + 32;   // this warp's point slice

    int segStart = p0;
    int tileEnd = p0 + TILE2;
    while (segStart < tileEnd) {
        int segEnd = g_offsets[c + 1];
        if (segEnd > tileEnd) segEnd = tileEnd;
        int lo = segStart - p0, hi = segEnd - p0;
        if (hi > lo) {
            bool fast = (lo == 0 && hi == TILE2);
            int cbase = c * DD * DD;

            {   // column sums: thread (w,l) covers col l, rows [wlo,whi) ∩ [lo,hi)
                int slo = lo > wlo ? lo : wlo;
                int shi = hi < whi ? hi : whi;
                float ssum = 0.f;
                for (int p = slo; p < shi; p++) ssum += sx[p * DD + l];
                if (shi > slo) atomicAdd(&g_sums[c * DD + l], ssum);
            }

            float acc[4][8];
#pragma unroll
            for (int a = 0; a < 4; a++)
#pragma unroll
                for (int b = 0; b < 8; b++) acc[a][b] = 0.f;

            int plo = lo > wlo ? lo : wlo;
            int phi = hi < whi ? hi : whi;
            if (phi - plo == 32) {
                const float* sp = sx + plo * DD;
#pragma unroll 8
                for (int p = 0; p < 32; p++) {
                    float4 rv  = *(const float4*)(sp + r4);
                    float4 cv0 = *(const float4*)(sp + c8);
                    float4 cv1 = *(const float4*)(sp + c8 + 4);
                    float rr[4] = {rv.x, rv.y, rv.z, rv.w};
                    float cc[8] = {cv0.x, cv0.y, cv0.z, cv0.w, cv1.x, cv1.y, cv1.z, cv1.w};
#pragma unroll
                    for (int a = 0; a < 4; a++)
#pragma unroll
                        for (int b = 0; b < 8; b++) acc[a][b] = fmaf(rr[a], cc[b], acc[a][b]);
                    sp += DD;
                }
            } else if (phi > plo) {
                const float* sp = sx + plo * DD;
                for (int p = plo; p < phi; p++) {
                    float4 rv  = *(const float4*)(sp + r4);
                    float4 cv0 = *(const float4*)(sp + c8);
                    float4 cv1 = *(const float4*)(sp + c8 + 4);
                    float rr[4] = {rv.x, rv.y, rv.z, rv.w};
                    float cc[8] = {cv0.x, cv0.y, cv0.z, cv0.w, cv1.x, cv1.y, cv1.z, cv1.w};
#pragma unroll
                    for (int a = 0; a < 4; a++)
#pragma unroll
                        for (int b = 0; b < 8; b++) acc[a][b] = fmaf(rr[a], cc[b], acc[a][b]);
                    sp += DD;
                }
            }

            if (fast) {
                // single segment == whole tile: merge 4 warps via smem (used once)
                float* dst = sm + (w * 32 + l) * 32;
#pragma unroll
                for (int a = 0; a < 4; a++)
#pragma unroll
                    for (int b = 0; b < 8; b++) dst[a * 8 + b] = acc[a][b];
                __syncthreads();
#pragma unroll
                for (int u = 0; u < 8; u++) {
                    int o = t * 8 + u;                 // 0..1023
                    int lane = o >> 5, reg = o & 31;
                    float s = sm[o] + sm[1024 + o] + sm[2048 + o] + sm[3072 + o];
                    int i = (lane >> 2) * 4 + (reg >> 3);
                    int j = (lane & 3) * 8 + (reg & 7);
                    atomicAdd(&g_m2[cbase + i * DD + j], s);
                }
            } else if (phi > plo) {
                // boundary tile (rare): direct per-warp atomics
#pragma unroll
                for (int a = 0; a < 4; a++)
#pragma unroll
                    for (int b = 0; b < 8; b++)
                        atomicAdd(&g_m2[cbase + (r4 + a) * DD + c8 + b], acc[a][b]);
            }
        }
        segStart = segEnd;
        c++;
    }
}

// ---------------- K5a: per-cluster stat loss partials (+re-zero m2/sums) ----------------
__global__ __launch_bounds__(256)
void k_stat(const float* __restrict__ means_t, const float* __restrict__ covs_t) {
    int k = blockIdx.x;
    int t = threadIdx.x;
    __shared__ float smean[DD];
    __shared__ float red[8];
    int cnt = g_counts[k];
    float inv = 1.0f / (float)(cnt > 0 ? cnt : 1);
    if (t < DD) smean[t] = g_sums[k * DD + t] * inv;
    __syncthreads();
    float lm = 0.f;
    if (t < DD) {
        float dm = smean[t] - means_t[k * DD + t];
        lm = dm * dm;
        g_sums[k * DD + t] = 0.f;
    }
    float lc = 0.f;
#pragma unroll
    for (int r = 0; r < 4; r++) {
        int idx = t + r * 256;
        int ii = idx >> 5, jj = idx & 31;
        float cov = g_m2[k * DD * DD + idx] * inv - smean[ii] * smean[jj];
        g_m2[k * DD * DD + idx] = 0.f;
        float dc = cov - covs_t[k * DD * DD + idx];
        lc = fmaf(dc, dc, lc);
    }
    float v = lm * (1.0f / (KK * DD)) + lc * (1.0f / (KK * DD * DD));
    v += __shfl_xor_sync(0xffffffffu, v, 16);
    v += __shfl_xor_sync(0xffffffffu, v, 8);
    v += __shfl_xor_sync(0xffffffffu, v, 4);
    v += __shfl_xor_sync(0xffffffffu, v, 2);
    v += __shfl_xor_sync(0xffffffffu, v, 1);
    if ((t & 31) == 0) red[t >> 5] = v;
    __syncthreads();
    if (t == 0) {
        float s = 0.f;
#pragma unroll
        for (int w = 0; w < 8; w++) s += red[w];
        atomicAdd(&g_acc[0], s);
    }
}

// ---------------- K5b: filling loss + final scalar (+re-zero fil/acc) ----------------
__global__ void k_final(const float* __restrict__ fil_t, float* __restrict__ out) {
    __shared__ float red[2];
    int t = threadIdx.x;  // 64 threads
    float f = g_fil[t] * (1.0f / NPTS) - fil_t[t];
    g_fil[t] = 0.f;
    float v = f * f;
    v += __shfl_xor_sync(0xffffffffu, v, 16);
    v += __shfl_xor_sync(0xffffffffu, v, 8);
    v += __shfl_xor_sync(0xffffffffu, v, 4);
    v += __shfl_xor_sync(0xffffffffu, v, 2);
    v += __shfl_xor_sync(0xffffffffu, v, 1);
    if ((t & 31) == 0) red[t >> 5] = v;
    __syncthreads();
    if (t == 0) {
        float a = g_acc[0];
        g_acc[0] = 0.f;
        out[0] = (red[0] + red[1]) * (1.0f / KK) + a;
    }
}

// ---------------- launcher (k_cov is profiled launch slot #4) ----------------
extern "C" void kernel_launch(void* const* d_in, const int* in_sizes, int n_in,
                              void* d_out, int out_size) {
    const float* x       = (const float*)d_in[0];
    const float* centers = (const float*)d_in[1];
    const float* fil_t   = (const float*)d_in[2];
    const float* means_t = (const float*)d_in[3];
    const float* covs_t  = (const float*)d_in[4];
    float* out = (float*)d_out;
    (void)in_sizes; (void)n_in; (void)out_size;

    k_assign<<<NBLK2, 256>>>(x, centers);
    k_prefix<<<1, 64>>>();
    k_order<<<NPTS / 1024, 256>>>();
    k_cov<<<NPTS / TILE2, 128>>>(x);
    k_stat<<<KK, 256>>>(means_t, covs_t);
    k_final<<<1, 64>>>(fil_t, out);
}

// round 15
// speedup vs baseline: 1.2350x; 1.2350x over previous
#include <cuda_runtime.h>

#define NPTS 131072
#define DD 32
#define KK 64
#define B2E 14.426950408889634f  /* BETA * log2(e), BETA=10 */
#define NBLK2 740                /* k_assign grid: 5 blocks/SM */
#define NWARPS (NBLK2 * 8)       /* 5920 counting warps */
#define NREP 32                  /* scatter cursor replicas */
#define TILE2 128                /* k_cov tile rows */

// ---------------- device scratch (zero-initialized at load; every kernel
// leaves its accumulators re-zeroed => graph replays start clean) ----------
__device__ int   g_ord[NPTS];              // cluster-sorted permutation
__device__ unsigned char g_pred[NPTS];
__device__ int   g_counts[KK];
__device__ int   g_counts2[KK * NREP];
__device__ int   g_cursor2[KK * NREP];
__device__ int   g_offsets[KK + 1];
__device__ float g_fil[KK];
__device__ float g_sums[KK * DD];
__device__ float g_m2[KK * DD * DD];
__device__ float g_acc[2];

// order-preserving float<->u32 key (min of key == min of float, bijective)
__device__ __forceinline__ unsigned ordkey(float f) {
    unsigned u = __float_as_uint(f);
    return u ^ (unsigned)(((int)u >> 31) | 0x80000000);
}
__device__ __forceinline__ float unord(unsigned k) {
    unsigned u = (k & 0x80000000u) ? (k ^ 0x80000000u) : ~k;
    return __uint_as_float(u);
}

// ---------------- K1: logits, softmax-filling, argmin, histogram ----------------
__global__ __launch_bounds__(256, 5)
void k_assign(const float* __restrict__ x, const float* __restrict__ centers) {
    __shared__ float sc[KK * DD];     // swizzled centers
    __shared__ float scn[KK];
    __shared__ float sfil[KK];
    __shared__ int   shist[KK];
    __shared__ float sxw[8][4][DD];

    int t = threadIdx.x, w = t >> 5, l = t & 31;

#pragma unroll
    for (int v = 0; v < 2; v++) {
        int idx = v * 256 + t;
        int r = idx >> 3, q = idx & 7;
        float4 val = ((const float4*)centers)[idx];
        int qs = q ^ (r & 7);
        *(float4*)&sc[r * DD + qs * 4] = val;
    }
    __syncthreads();
    if (t < KK) {
        float a = 0.f;
#pragma unroll
        for (int q = 0; q < 8; q++) {
            int qs = q ^ (t & 7);
            float4 v = *(const float4*)&sc[t * DD + qs * 4];
            a = fmaf(v.x, v.x, fmaf(v.y, v.y, fmaf(v.z, v.z, fmaf(v.w, v.w, a))));
        }
        scn[t] = a;
        sfil[t] = 0.f; shist[t] = 0;
    }
    __syncthreads();

    float cn0 = scn[l], cn1 = scn[l + 32];
    const float* c0base = sc + l * DD;
    const float* c1base = sc + (l + 32) * DD;
    int sw = (l & 7);

    float fil0 = 0.f, fil1 = 0.f;
    int W = blockIdx.x * 8 + w;

    for (int n0 = W * 4; n0 < NPTS; n0 += NWARPS * 4) {
        float xp[4];
#pragma unroll
        for (int p = 0; p < 4; p++) xp[p] = x[(size_t)(n0 + p) * DD + l];
        __syncwarp();
#pragma unroll
        for (int p = 0; p < 4; p++) sxw[w][p][l] = xp[p];
        __syncwarp();

        float d0[4] = {0.f, 0.f, 0.f, 0.f};
        float d1[4] = {0.f, 0.f, 0.f, 0.f};
#pragma unroll
        for (int q = 0; q < 8; q++) {
            int qs = (q ^ sw) * 4;
            float4 cv0 = *(const float4*)&c0base[qs];
            float4 cv1 = *(const float4*)&c1base[qs];
#pragma unroll
            for (int p = 0; p < 4; p++) {
                float4 xv = *(const float4*)&sxw[w][p][q * 4];
                d0[p] = fmaf(cv0.x, xv.x, d0[p]);
                d0[p] = fmaf(cv0.y, xv.y, d0[p]);
                d0[p] = fmaf(cv0.z, xv.z, d0[p]);
                d0[p] = fmaf(cv0.w, xv.w, d0[p]);
                d1[p] = fmaf(cv1.x, xv.x, d1[p]);
                d1[p] = fmaf(cv1.y, xv.y, d1[p]);
                d1[p] = fmaf(cv1.z, xv.z, d1[p]);
                d1[p] = fmaf(cv1.w, xv.w, d1[p]);
            }
        }

        float s0a[4], s1a[4];
#pragma unroll
        for (int p = 0; p < 4; p++) {
            s0a[p] = fmaf(-2.f, d0[p], cn0);
            s1a[p] = fmaf(-2.f, d1[p], cn1);
        }

        unsigned k0v[4], k1v[4], mk[4];
#pragma unroll
        for (int p = 0; p < 4; p++) { k0v[p] = ordkey(s0a[p]); k1v[p] = ordkey(s1a[p]); }
#pragma unroll
        for (int p = 0; p < 4; p++)
            mk[p] = __reduce_min_sync(0xffffffffu, min(k0v[p], k1v[p]));
        int id[4];
#pragma unroll
        for (int p = 0; p < 4; p++) {
            unsigned cand = (k0v[p] == mk[p]) ? (unsigned)l
                          : ((k1v[p] == mk[p]) ? (unsigned)(l + 32) : 1024u);
            id[p] = (int)__reduce_min_sync(0xffffffffu, cand);
        }

        float e0[4], e1[4], es[4];
#pragma unroll
        for (int p = 0; p < 4; p++) {
            float mn = unord(mk[p]);
            asm("ex2.approx.f32 %0, %1;" : "=f"(e0[p]) : "f"((mn - s0a[p]) * B2E));
            asm("ex2.approx.f32 %0, %1;" : "=f"(e1[p]) : "f"((mn - s1a[p]) * B2E));
            es[p] = e0[p] + e1[p];
        }
#pragma unroll
        for (int off = 16; off; off >>= 1) {
#pragma unroll
            for (int p = 0; p < 4; p++)
                es[p] += __shfl_xor_sync(0xffffffffu, es[p], off);
        }

        unsigned pred4 = 0;
#pragma unroll
        for (int p = 0; p < 4; p++) {
            float inv;
            asm("rcp.approx.f32 %0, %1;" : "=f"(inv) : "f"(es[p]));
            fil0 = fmaf(e0[p], inv, fil0);
            fil1 = fmaf(e1[p], inv, fil1);
            pred4 |= (unsigned)id[p] << (8 * p);
            if (l == p) atomicAdd(&shist[id[p]], 1);
        }
        if (l == 0) *(unsigned*)(g_pred + n0) = pred4;
    }

    atomicAdd(&sfil[l], fil0);
    atomicAdd(&sfil[l + 32], fil1);
    __syncthreads();
    if (t < KK) {
        atomicAdd(&g_fil[t], sfil[t]);
        atomicAdd(&g_counts2[t * NREP + (blockIdx.x & (NREP - 1))], shist[t]);
    }
}

// ---------------- K2: prefix over 64 clusters x 32 replicas (+re-zero) ----------------
__global__ void k_prefix() {
    __shared__ int csum[KK];
    int t = threadIdx.x;   // 64 threads
    int c[NREP];
    int total = 0;
#pragma unroll
    for (int r = 0; r < NREP; r++) {
        c[r] = g_counts2[t * NREP + r];
        g_counts2[t * NREP + r] = 0;
        total += c[r];
    }
    csum[t] = total;
    __syncthreads();
    if (t == 0) {
        int a = 0;
        for (int k = 0; k < KK; k++) { g_offsets[k] = a; a += csum[k]; }
        g_offsets[KK] = a;
    }
    __syncthreads();
    int a = g_offsets[t];
#pragma unroll
    for (int r = 0; r < NREP; r++) { g_cursor2[t * NREP + r] = a; a += c[r]; }
    g_counts[t] = total;
}

// ---------------- K3: permutation only (no data movement) ----------------
__global__ __launch_bounds__(256)
void k_order() {
    int i0 = (blockIdx.x * 256 + threadIdx.x) * 4;
    if (i0 >= NPTS) return;
    unsigned pr = *(const unsigned*)(g_pred + i0);
    int rep = (((i0 >> 2) % NWARPS) >> 3) & (NREP - 1);
#pragma unroll
    for (int p = 0; p < 4; p++) {
        int k = (pr >> (8 * p)) & 255;
        int pos = atomicAdd(&g_cursor2[k * NREP + rep], 1);
        g_ord[pos] = i0 + p;
    }
}

// ---------------- K4: 128-row tiles; warps own disjoint 8-row output slices ---
// Warp w owns output rows [8w, 8w+8) x all 32 cols; every warp scans all tile
// points. Per point/lane: 1 lane-col LDS + 2 uniform LDS.128 + 8 FMA.
// No cross-warp merge; segment-end REDGs go straight to g_m2.
__global__ __launch_bounds__(128)
void k_cov(const float* __restrict__ x) {
    __shared__ float sx[TILE2 * DD];          // 16 KB tile
    __shared__ int sord[TILE2];
    int t = threadIdx.x, w = t >> 5, l = t & 31;
    int p0 = blockIdx.x * TILE2;

    sord[t] = g_ord[p0 + t];
    __syncthreads();

    {   // gather tile: 8 consecutive threads read same row, consecutive chunks
        float4* sv = (float4*)sx;
        const float4* xv = (const float4*)x;
#pragma unroll
        for (int v = 0; v < 8; v++) {
            int li = v * 128 + t;              // 0..1023
            int row = li >> 3, chunk = li & 7;
            sv[li] = xv[(size_t)sord[row] * 8 + chunk];
        }
    }
    __syncthreads();

    // cluster containing row p0
    int lo_c = 0, hi_c = KK;
    while (lo_c + 1 < hi_c) {
        int mid = (lo_c + hi_c) >> 1;
        if (g_offsets[mid] <= p0) lo_c = mid; else hi_c = mid;
    }
    int c = lo_c;

    int rbase = w * 8;         // this warp's output rows [rbase, rbase+8)

    int segStart = p0;
    int tileEnd = p0 + TILE2;
    while (segStart < tileEnd) {
        int segEnd = g_offsets[c + 1];
        if (segEnd > tileEnd) segEnd = tileEnd;
        int lo = segStart - p0, hi = segEnd - p0;
        if (hi > lo) {
            float acc[8];
#pragma unroll
            for (int a = 0; a < 8; a++) acc[a] = 0.f;
            float ssum = 0.f;

            if (lo == 0 && hi == TILE2) {
                const float* sp = sx;
#pragma unroll 4
                for (int p = 0; p < TILE2; p++) {
                    float xl = sp[l];
                    float4 u0 = *(const float4*)(sp + rbase);
                    float4 u1 = *(const float4*)(sp + rbase + 4);
                    acc[0] = fmaf(u0.x, xl, acc[0]); acc[1] = fmaf(u0.y, xl, acc[1]);
                    acc[2] = fmaf(u0.z, xl, acc[2]); acc[3] = fmaf(u0.w, xl, acc[3]);
                    acc[4] = fmaf(u1.x, xl, acc[4]); acc[5] = fmaf(u1.y, xl, acc[5]);
                    acc[6] = fmaf(u1.z, xl, acc[6]); acc[7] = fmaf(u1.w, xl, acc[7]);
                    if ((p & 3) == w) ssum += xl;   // distribute colsum over warps
                    sp += DD;
                }
            } else {
                const float* sp = sx + lo * DD;
                for (int p = lo; p < hi; p++) {
                    float xl = sp[l];
                    float4 u0 = *(const float4*)(sp + rbase);
                    float4 u1 = *(const float4*)(sp + rbase + 4);
                    acc[0] = fmaf(u0.x, xl, acc[0]); acc[1] = fmaf(u0.y, xl, acc[1]);
                    acc[2] = fmaf(u0.z, xl, acc[2]); acc[3] = fmaf(u0.w, xl, acc[3]);
                    acc[4] = fmaf(u1.x, xl, acc[4]); acc[5] = fmaf(u1.y, xl, acc[5]);
                    acc[6] = fmaf(u1.z, xl, acc[6]); acc[7] = fmaf(u1.w, xl, acc[7]);
                    if (((p - lo) & 3) == w) ssum += xl;
                    sp += DD;
                }
            }

            int base = c * DD * DD + rbase * DD + l;
#pragma unroll
            for (int a = 0; a < 8; a++)
                atomicAdd(&g_m2[base + a * DD], acc[a]);
            atomicAdd(&g_sums[c * DD + l], ssum);
        }
        segStart = segEnd;
        c++;
    }
}

// ---------------- K5a: per-cluster stat loss partials (+re-zero m2/sums) ----------------
__global__ __launch_bounds__(256)
void k_stat(const float* __restrict__ means_t, const float* __restrict__ covs_t) {
    int k = blockIdx.x;
    int t = threadIdx.x;
    __shared__ float smean[DD];
    __shared__ float red[8];
    int cnt = g_counts[k];
    float inv = 1.0f / (float)(cnt > 0 ? cnt : 1);
    if (t < DD) smean[t] = g_sums[k * DD + t] * inv;
    __syncthreads();
    float lm = 0.f;
    if (t < DD) {
        float dm = smean[t] - means_t[k * DD + t];
        lm = dm * dm;
        g_sums[k * DD + t] = 0.f;
    }
    float lc = 0.f;
#pragma unroll
    for (int r = 0; r < 4; r++) {
        int idx = t + r * 256;
        int ii = idx >> 5, jj = idx & 31;
        float cov = g_m2[k * DD * DD + idx] * inv - smean[ii] * smean[jj];
        g_m2[k * DD * DD + idx] = 0.f;
        float dc = cov - covs_t[k * DD * DD + idx];
        lc = fmaf(dc, dc, lc);
    }
    float v = lm * (1.0f / (KK * DD)) + lc * (1.0f / (KK * DD * DD));
    v += __shfl_xor_sync(0xffffffffu, v, 16);
    v += __shfl_xor_sync(0xffffffffu, v, 8);
    v += __shfl_xor_sync(0xffffffffu, v, 4);
    v += __shfl_xor_sync(0xffffffffu, v, 2);
    v += __shfl_xor_sync(0xffffffffu, v, 1);
    if ((t & 31) == 0) red[t >> 5] = v;
    __syncthreads();
    if (t == 0) {
        float s = 0.f;
#pragma unroll
        for (int w = 0; w < 8; w++) s += red[w];
        atomicAdd(&g_acc[0], s);
    }
}

// ---------------- K5b: filling loss + final scalar (+re-zero fil/acc) ----------------
__global__ void k_final(const float* __restrict__ fil_t, float* __restrict__ out) {
    __shared__ float red[2];
    int t = threadIdx.x;  // 64 threads
    float f = g_fil[t] * (1.0f / NPTS) - fil_t[t];
    g_fil[t] = 0.f;
    float v = f * f;
    v += __shfl_xor_sync(0xffffffffu, v, 16);
    v += __shfl_xor_sync(0xffffffffu, v, 8);
    v += __shfl_xor_sync(0xffffffffu, v, 4);
    v += __shfl_xor_sync(0xffffffffu, v, 2);
    v += __shfl_xor_sync(0xffffffffu, v, 1);
    if ((t & 31) == 0) red[t >> 5] = v;
    __syncthreads();
    if (t == 0) {
        float a = g_acc[0];
        g_acc[0] = 0.f;
        out[0] = (red[0] + red[1]) * (1.0f / KK) + a;
    }
}

// ---------------- launcher (k_cov is profiled launch slot #4) ----------------
extern "C" void kernel_launch(void* const* d_in, const int* in_sizes, int n_in,
                              void* d_out, int out_size) {
    const float* x       = (const float*)d_in[0];
    const float* centers = (const float*)d_in[1];
    const float* fil_t   = (const float*)d_in[2];
    const float* means_t = (const float*)d_in[3];
    const float* covs_t  = (const float*)d_in[4];
    float* out = (float*)d_out;
    (void)in_sizes; (void)n_in; (void)out_size;

    k_assign<<<NBLK2, 256>>>(x, centers);
    k_prefix<<<1, 64>>>();
    k_order<<<NPTS / 1024, 256>>>();
    k_cov<<<NPTS / TILE2, 128>>>(x);
    k_stat<<<KK, 256>>>(means_t, covs_t);
    k_final<<<1, 64>>>(fil_t, out);
}